// round 1
// baseline (speedup 1.0000x reference)
#include <cuda_runtime.h>
#include <cuda_fp16.h>
#include <cstdint>

// NT-Xent loss, fused: normalize -> f16 MMA Gram tiles -> exp/row-sum epilogue
// -> per-row logsumexp - positive -> mean.
//
// N = 8192 rows (2*B), D = 128, T = 0.5 (logit scale = 2). cos <= 1 so
// logits <= 2: logsumexp needs no running max; direct exp-sum in fp32 is safe.

#define N_TOT 8192
#define DIM   128
#define B_HALF 4096
#define BM 128
#define BN 128
#define KC 64
#define LDS 80              // smem row stride in halves (160B: 16B-aligned, banks shift 32B/row)
#define NJT (N_TOT / BN)    // 64 j-tiles

__device__ __half g_zn_h[N_TOT * DIM];        // normalized rows, fp16 (MMA operands)
__device__ float  g_zn_f[N_TOT * DIM];        // normalized rows, fp32 (positive-pair dots)
__device__ float  g_partial[NJT * N_TOT];     // [jt][i] partial exp-sums
__device__ float  g_loss[N_TOT];              // per-row loss

// ---------------------------------------------------------------------------
// Kernel 1: row normalization. One warp per row.
// ---------------------------------------------------------------------------
__global__ void k_normalize(const float* __restrict__ zi, const float* __restrict__ zj) {
    int warp = (blockIdx.x * blockDim.x + threadIdx.x) >> 5;
    int lane = threadIdx.x & 31;
    if (warp >= N_TOT) return;
    const float* src = (warp < B_HALF) ? (zi + warp * DIM) : (zj + (warp - B_HALF) * DIM);
    float4 v = ((const float4*)src)[lane];
    float ss = v.x * v.x + v.y * v.y + v.z * v.z + v.w * v.w;
    #pragma unroll
    for (int o = 16; o; o >>= 1) ss += __shfl_xor_sync(0xffffffffu, ss, o);
    float inv = rsqrtf(ss);
    float4 n = make_float4(v.x * inv, v.y * inv, v.z * inv, v.w * inv);
    ((float4*)(g_zn_f + warp * DIM))[lane] = n;
    __half2* hdst = (__half2*)(g_zn_h + warp * DIM);
    hdst[lane * 2]     = __floats2half2_rn(n.x, n.y);
    hdst[lane * 2 + 1] = __floats2half2_rn(n.z, n.w);
}

// ---------------------------------------------------------------------------
// MMA helpers
// ---------------------------------------------------------------------------
__device__ __forceinline__ void ldsm_x4(uint32_t addr, uint32_t& r0, uint32_t& r1,
                                        uint32_t& r2, uint32_t& r3) {
    asm volatile("ldmatrix.sync.aligned.m8n8.x4.shared.b16 {%0,%1,%2,%3}, [%4];"
                 : "=r"(r0), "=r"(r1), "=r"(r2), "=r"(r3) : "r"(addr));
}

__device__ __forceinline__ void mma16816(float* c, const uint32_t* a, const uint32_t* b) {
    asm volatile("mma.sync.aligned.m16n8k16.row.col.f32.f16.f16.f32 "
                 "{%0,%1,%2,%3}, {%4,%5,%6,%7}, {%8,%9}, {%0,%1,%2,%3};"
                 : "+f"(c[0]), "+f"(c[1]), "+f"(c[2]), "+f"(c[3])
                 : "r"(a[0]), "r"(a[1]), "r"(a[2]), "r"(a[3]), "r"(b[0]), "r"(b[1]));
}

// ---------------------------------------------------------------------------
// Kernel 2: Gram tile + exp + row partial sums.
// Block = 128x128 output tile, 256 threads = 8 warps (4 in M x 2 in N),
// warp tile 32x64 -> 2x8 mma tiles of 16x8, K looped in 64-wide smem chunks.
// ---------------------------------------------------------------------------
__global__ void __launch_bounds__(256) k_simexp() {
    __shared__ __half As[BM * LDS];
    __shared__ __half Bs[BN * LDS];
    __shared__ float  red[2][BM];

    const int jt = blockIdx.x, it = blockIdx.y;
    const int i0 = it * BM, j0 = jt * BN;
    const int tid  = threadIdx.x;
    const int warp = tid >> 5, lane = tid & 31;
    const int wm = warp >> 1;   // 0..3 : 32 rows each
    const int wn = warp & 1;    // 0..1 : 64 cols each

    float c[2][8][4];
    #pragma unroll
    for (int a = 0; a < 2; a++)
        #pragma unroll
        for (int b = 0; b < 8; b++)
            #pragma unroll
            for (int e = 0; e < 4; e++) c[a][b][e] = 0.f;

    for (int kc = 0; kc < DIM; kc += KC) {
        __syncthreads();
        // Stage A (rows i0..i0+127) and B (rows j0..j0+127), 64-half k-slices.
        // 128 rows * 8 segments of 16B = 1024 segs each; 4 per thread.
        #pragma unroll
        for (int s = 0; s < 4; s++) {
            int idx = tid + 256 * s;
            int row = idx >> 3, seg = idx & 7;
            *(float4*)(As + row * LDS + seg * 8) =
                *(const float4*)(g_zn_h + (i0 + row) * DIM + kc + seg * 8);
            *(float4*)(Bs + row * LDS + seg * 8) =
                *(const float4*)(g_zn_h + (j0 + row) * DIM + kc + seg * 8);
        }
        __syncthreads();

        #pragma unroll
        for (int ks = 0; ks < KC; ks += 16) {
            uint32_t af[2][4];
            #pragma unroll
            for (int mt = 0; mt < 2; mt++) {
                int row = wm * 32 + mt * 16 + (lane & 15);
                int col = ks + 8 * (lane >> 4);
                uint32_t addr = (uint32_t)__cvta_generic_to_shared(As + row * LDS + col);
                ldsm_x4(addr, af[mt][0], af[mt][1], af[mt][2], af[mt][3]);
            }
            uint32_t bf[8][2];
            #pragma unroll
            for (int np = 0; np < 4; np++) {   // two n-tiles per ldmatrix.x4
                int quad = lane >> 3, within = lane & 7;
                int n = wn * 64 + np * 16 + (quad >> 1) * 8 + within;
                int k = ks + (quad & 1) * 8;
                uint32_t addr = (uint32_t)__cvta_generic_to_shared(Bs + n * LDS + k);
                uint32_t r0, r1, r2, r3;
                ldsm_x4(addr, r0, r1, r2, r3);
                bf[np * 2][0] = r0;     bf[np * 2][1] = r1;
                bf[np * 2 + 1][0] = r2; bf[np * 2 + 1][1] = r3;
            }
            #pragma unroll
            for (int mt = 0; mt < 2; mt++)
                #pragma unroll
                for (int nt = 0; nt < 8; nt++)
                    mma16816(c[mt][nt], af[mt], bf[nt]);
        }
    }

    // Epilogue: e = exp(2*sim) (skip diagonal), reduce to per-row partials.
    #pragma unroll
    for (int mt = 0; mt < 2; mt++) {
        #pragma unroll
        for (int rh = 0; rh < 2; rh++) {
            int lrow = wm * 32 + mt * 16 + rh * 8 + (lane >> 2);
            int gi = i0 + lrow;
            float s = 0.f;
            #pragma unroll
            for (int nt = 0; nt < 8; nt++) {
                #pragma unroll
                for (int e = 0; e < 2; e++) {
                    int gj = j0 + wn * 64 + nt * 8 + (lane & 3) * 2 + e;
                    float v = c[mt][nt][rh * 2 + e];
                    if (gi != gj) s += __expf(2.0f * v);
                }
            }
            s += __shfl_xor_sync(0xffffffffu, s, 1);
            s += __shfl_xor_sync(0xffffffffu, s, 2);
            if ((lane & 3) == 0) red[wn][lrow] = s;
        }
    }
    __syncthreads();
    if (tid < BM)
        g_partial[jt * N_TOT + i0 + tid] = red[0][tid] + red[1][tid];
}

// ---------------------------------------------------------------------------
// Kernel 3: per-row loss = log(S_i) - 2*dot(zn_i, zn_partner). Warp per row.
// ---------------------------------------------------------------------------
__global__ void k_rowloss() {
    int i = (blockIdx.x * blockDim.x + threadIdx.x) >> 5;
    int lane = threadIdx.x & 31;
    if (i >= N_TOT) return;
    float S = g_partial[lane * N_TOT + i] + g_partial[(lane + 32) * N_TOT + i];
    int p = (i < B_HALF) ? (i + B_HALF) : (i - B_HALF);
    float4 x = ((const float4*)(g_zn_f + i * DIM))[lane];
    float4 y = ((const float4*)(g_zn_f + p * DIM))[lane];
    float dot = x.x * y.x + x.y * y.y + x.z * y.z + x.w * y.w;
    #pragma unroll
    for (int o = 16; o; o >>= 1) {
        S   += __shfl_xor_sync(0xffffffffu, S, o);
        dot += __shfl_xor_sync(0xffffffffu, dot, o);
    }
    if (lane == 0) g_loss[i] = logf(S) - 2.0f * dot;
}

// ---------------------------------------------------------------------------
// Kernel 4: mean over rows -> scalar. Single block, fixed order.
// ---------------------------------------------------------------------------
__global__ void k_final(float* __restrict__ out) {
    __shared__ float sm[256];
    int t = threadIdx.x;
    float s = 0.f;
    for (int k = t; k < N_TOT; k += 256) s += g_loss[k];
    sm[t] = s;
    __syncthreads();
    #pragma unroll
    for (int o = 128; o; o >>= 1) {
        if (t < o) sm[t] += sm[t + o];
        __syncthreads();
    }
    if (t == 0) out[0] = sm[0] / (float)N_TOT;
}

// ---------------------------------------------------------------------------
extern "C" void kernel_launch(void* const* d_in, const int* in_sizes, int n_in,
                              void* d_out, int out_size) {
    const float* zi = (const float*)d_in[0];
    const float* zj = (const float*)d_in[1];
    (void)in_sizes; (void)n_in; (void)out_size;

    k_normalize<<<N_TOT / 8, 256>>>(zi, zj);
    dim3 grid(N_TOT / BN, N_TOT / BM);
    k_simexp<<<grid, 256>>>();
    k_rowloss<<<N_TOT / 8, 256>>>();
    k_final<<<1, 256>>>((float*)d_out);
}

// round 4
// speedup vs baseline: 1.4001x; 1.4001x over previous
#include <cuda_runtime.h>
#include <cuda_fp16.h>
#include <cstdint>

// NT-Xent loss, symmetric-Gram fused pipeline:
//   normalize -> f16 mma.sync Gram tiles (upper triangle only; each block
//   emits row-partials AND column-partials) -> per-row lse - positive -> mean.
// N = 8192, D = 128, T = 0.5 (logit scale 2; cos<=1 so lse needs no max).

#define N_TOT  8192
#define DIM    128
#define B_HALF 4096
#define BM     128
#define BN     128
#define LDS    136              // smem row stride in halves (272B; ldmatrix conflict-free)
#define NJT    (N_TOT / BN)     // 64 tile rows/cols

#define SM_A    0
#define SM_B    (BM * LDS * 2)              // 34816
#define SM_RED  (SM_B + BN * LDS * 2)       // 69632 : float red[2][128]
#define SM_CRED (SM_RED + 1024)             // 70656 : float colred[4][128]
#define SMEM_SZ (SM_CRED + 2048)            // 72704 bytes

__device__ __half g_zn_h[N_TOT * DIM];      // normalized rows, fp16 (MMA operands)
__device__ float  g_zn_f[N_TOT * DIM];      // normalized rows, fp32 (positive dots)
__device__ float  g_partial[NJT * N_TOT];   // [tile][row] partial exp-sums
__device__ float  g_loss[N_TOT];
__device__ float  g_bsum[64];

// ---------------------------------------------------------------------------
// Kernel 1: row normalization. One warp per row.
// ---------------------------------------------------------------------------
__global__ void k_normalize(const float* __restrict__ zi, const float* __restrict__ zj) {
    int warp = (blockIdx.x * blockDim.x + threadIdx.x) >> 5;
    int lane = threadIdx.x & 31;
    if (warp >= N_TOT) return;
    const float* src = (warp < B_HALF) ? (zi + warp * DIM) : (zj + (warp - B_HALF) * DIM);
    float4 v = ((const float4*)src)[lane];
    float ss = v.x * v.x + v.y * v.y + v.z * v.z + v.w * v.w;
    #pragma unroll
    for (int o = 16; o; o >>= 1) ss += __shfl_xor_sync(0xffffffffu, ss, o);
    float inv = rsqrtf(ss);
    float4 n = make_float4(v.x * inv, v.y * inv, v.z * inv, v.w * inv);
    ((float4*)(g_zn_f + warp * DIM))[lane] = n;
    __half2* hdst = (__half2*)(g_zn_h + warp * DIM);
    hdst[lane * 2]     = __floats2half2_rn(n.x, n.y);
    hdst[lane * 2 + 1] = __floats2half2_rn(n.z, n.w);
}

// ---------------------------------------------------------------------------
// MMA helpers
// ---------------------------------------------------------------------------
__device__ __forceinline__ void ldsm_x4(uint32_t addr, uint32_t& r0, uint32_t& r1,
                                        uint32_t& r2, uint32_t& r3) {
    asm volatile("ldmatrix.sync.aligned.m8n8.x4.shared.b16 {%0,%1,%2,%3}, [%4];"
                 : "=r"(r0), "=r"(r1), "=r"(r2), "=r"(r3) : "r"(addr));
}

__device__ __forceinline__ void mma16816(float* c, const uint32_t* a, const uint32_t* b) {
    asm volatile("mma.sync.aligned.m16n8k16.row.col.f32.f16.f16.f32 "
                 "{%0,%1,%2,%3}, {%4,%5,%6,%7}, {%8,%9}, {%0,%1,%2,%3};"
                 : "+f"(c[0]), "+f"(c[1]), "+f"(c[2]), "+f"(c[3])
                 : "r"(a[0]), "r"(a[1]), "r"(a[2]), "r"(a[3]), "r"(b[0]), "r"(b[1]));
}

// ---------------------------------------------------------------------------
// Kernel 2: 128x128 Gram tile, upper triangle (jt >= it).
// 256 threads = 8 warps (4 in M x 2 in N), warp tile 32x64.
// Emits row-partials (-> g_partial[jt][i-rows]) and, for jt>it,
// column-partials (-> g_partial[it][j-rows]) from the same exp values.
// ---------------------------------------------------------------------------
__global__ void __launch_bounds__(256, 1) k_simexp() {
    const int jt = blockIdx.x, it = blockIdx.y;
    if (jt < it) return;
    extern __shared__ char smem[];
    __half* As = (__half*)(smem + SM_A);
    __half* Bs = (__half*)(smem + SM_B);
    float*  red    = (float*)(smem + SM_RED);    // [2][128]
    float*  colred = (float*)(smem + SM_CRED);   // [4][128]

    const int i0 = it * BM, j0 = jt * BN;
    const int tid  = threadIdx.x;
    const int warp = tid >> 5, lane = tid & 31;
    const int wm = warp >> 1;   // 0..3 : 32 rows
    const int wn = warp & 1;    // 0..1 : 64 cols
    const bool diag = (it == jt);

    // Stage full-K operands: 128 rows x 16 x 8-half segments each.
    #pragma unroll
    for (int s = 0; s < 8; s++) {
        int idx = tid + 256 * s;
        int row = idx >> 4, seg = idx & 15;
        *(float4*)(As + row * LDS + seg * 8) =
            *(const float4*)(g_zn_h + (i0 + row) * DIM + seg * 8);
        *(float4*)(Bs + row * LDS + seg * 8) =
            *(const float4*)(g_zn_h + (j0 + row) * DIM + seg * 8);
    }
    __syncthreads();

    float c[2][8][4];
    #pragma unroll
    for (int a = 0; a < 2; a++)
        #pragma unroll
        for (int b = 0; b < 8; b++)
            #pragma unroll
            for (int e = 0; e < 4; e++) c[a][b][e] = 0.f;

    #pragma unroll
    for (int ks = 0; ks < DIM; ks += 16) {
        uint32_t af[2][4];
        #pragma unroll
        for (int mt = 0; mt < 2; mt++) {
            int row = wm * 32 + mt * 16 + (lane & 15);
            int col = ks + 8 * (lane >> 4);
            uint32_t addr = (uint32_t)__cvta_generic_to_shared(As + row * LDS + col);
            ldsm_x4(addr, af[mt][0], af[mt][1], af[mt][2], af[mt][3]);
        }
        uint32_t bf[8][2];
        #pragma unroll
        for (int np = 0; np < 4; np++) {
            int quad = lane >> 3, within = lane & 7;
            int n = wn * 64 + np * 16 + (quad >> 1) * 8 + within;
            int k = ks + (quad & 1) * 8;
            uint32_t addr = (uint32_t)__cvta_generic_to_shared(Bs + n * LDS + k);
            uint32_t r0, r1, r2, r3;
            ldsm_x4(addr, r0, r1, r2, r3);
            bf[np * 2][0] = r0;     bf[np * 2][1] = r1;
            bf[np * 2 + 1][0] = r2; bf[np * 2 + 1][1] = r3;
        }
        #pragma unroll
        for (int mt = 0; mt < 2; mt++)
            #pragma unroll
            for (int nt = 0; nt < 8; nt++)
                mma16816(c[mt][nt], af[mt], bf[nt]);
    }

    // Epilogue: ev = exp(2*sim); accumulate row sums and column sums.
    float rowsum[4] = {0.f, 0.f, 0.f, 0.f};   // [mt*2+rh]
    float colacc[16];                          // [nt*2+e]
    #pragma unroll
    for (int q = 0; q < 16; q++) colacc[q] = 0.f;

    #pragma unroll
    for (int mt = 0; mt < 2; mt++) {
        #pragma unroll
        for (int nt = 0; nt < 8; nt++) {
            #pragma unroll
            for (int rh = 0; rh < 2; rh++) {
                #pragma unroll
                for (int e = 0; e < 2; e++) {
                    float v = c[mt][nt][rh * 2 + e];
                    float ev = __expf(2.0f * v);
                    if (diag) {
                        int lrow = wm * 32 + mt * 16 + rh * 8 + (lane >> 2);
                        int lcol = wn * 64 + nt * 8 + (lane & 3) * 2 + e;
                        if (lrow == lcol) ev = 0.f;
                    }
                    rowsum[mt * 2 + rh] += ev;
                    colacc[nt * 2 + e]  += ev;
                }
            }
        }
    }

    // Row reduction: sum over the 4 column-lanes of each row.
    #pragma unroll
    for (int mt = 0; mt < 2; mt++) {
        #pragma unroll
        for (int rh = 0; rh < 2; rh++) {
            float s = rowsum[mt * 2 + rh];
            s += __shfl_xor_sync(0xffffffffu, s, 1);
            s += __shfl_xor_sync(0xffffffffu, s, 2);
            if ((lane & 3) == 0) {
                int lrow = wm * 32 + mt * 16 + rh * 8 + (lane >> 2);
                red[wn * BM + lrow] = s;
            }
        }
    }

    // Column reduction: sum over the 8 row-lane-groups; all lanes end full.
    #pragma unroll
    for (int q = 0; q < 16; q++) {
        float s = colacc[q];
        s += __shfl_xor_sync(0xffffffffu, s, 4);
        s += __shfl_xor_sync(0xffffffffu, s, 8);
        s += __shfl_xor_sync(0xffffffffu, s, 16);
        colacc[q] = s;
    }
    if (lane < 4) {
        #pragma unroll
        for (int q = 0; q < 16; q++) {
            int lcol = wn * 64 + (q >> 1) * 8 + lane * 2 + (q & 1);
            colred[wm * BN + lcol] = colacc[q];
        }
    }
    __syncthreads();

    if (tid < BM)
        g_partial[jt * N_TOT + i0 + tid] = red[tid] + red[BM + tid];
    if (!diag && tid < BN)
        g_partial[it * N_TOT + j0 + tid] =
            colred[tid] + colred[BN + tid] + colred[2 * BN + tid] + colred[3 * BN + tid];
}

// ---------------------------------------------------------------------------
// Kernel 3: per-row loss = log(S_i) - 2*dot_f32(zn_i, zn_partner). Warp/row.
// ---------------------------------------------------------------------------
__global__ void k_rowloss() {
    int i = (blockIdx.x * blockDim.x + threadIdx.x) >> 5;
    int lane = threadIdx.x & 31;
    if (i >= N_TOT) return;
    float S = g_partial[lane * N_TOT + i] + g_partial[(lane + 32) * N_TOT + i];
    int p = (i < B_HALF) ? (i + B_HALF) : (i - B_HALF);
    float4 x = ((const float4*)(g_zn_f + i * DIM))[lane];
    float4 y = ((const float4*)(g_zn_f + p * DIM))[lane];
    float dot = x.x * y.x + x.y * y.y + x.z * y.z + x.w * y.w;
    #pragma unroll
    for (int o = 16; o; o >>= 1) {
        S   += __shfl_xor_sync(0xffffffffu, S, o);
        dot += __shfl_xor_sync(0xffffffffu, dot, o);
    }
    if (lane == 0) g_loss[i] = logf(S) - 2.0f * dot;
}

// ---------------------------------------------------------------------------
// Kernels 4a/4b: two-stage deterministic mean.
// ---------------------------------------------------------------------------
__global__ void k_final_a() {
    __shared__ float sm[128];
    int t = threadIdx.x, b = blockIdx.x;
    sm[t] = g_loss[b * 128 + t];
    __syncthreads();
    #pragma unroll
    for (int o = 64; o; o >>= 1) {
        if (t < o) sm[t] += sm[t + o];
        __syncthreads();
    }
    if (t == 0) g_bsum[b] = sm[0];
}

__global__ void k_final_b(float* __restrict__ out) {
    int t = threadIdx.x;          // one warp
    float s = g_bsum[t] + g_bsum[t + 32];
    #pragma unroll
    for (int o = 16; o; o >>= 1) s += __shfl_xor_sync(0xffffffffu, s, o);
    if (t == 0) out[0] = s / (float)N_TOT;
}

// ---------------------------------------------------------------------------
extern "C" void kernel_launch(void* const* d_in, const int* in_sizes, int n_in,
                              void* d_out, int out_size) {
    const float* zi = (const float*)d_in[0];
    const float* zj = (const float*)d_in[1];
    (void)in_sizes; (void)n_in; (void)out_size;

    cudaFuncSetAttribute(k_simexp, cudaFuncAttributeMaxDynamicSharedMemorySize, SMEM_SZ);

    k_normalize<<<N_TOT / 8, 256>>>(zi, zj);
    dim3 grid(NJT, NJT);
    k_simexp<<<grid, 256, SMEM_SZ>>>();
    k_rowloss<<<N_TOT / 8, 256>>>();
    k_final_a<<<64, 128>>>();
    k_final_b<<<1, 32>>>((float*)d_out);
}